// round 1
// baseline (speedup 1.0000x reference)
#include <cuda_runtime.h>

// QuantumLayer: 4-qubit circuit, closed-form.
//   z_q   = cos(theta_q)*cos(x_q) - cos(phi_q)*sin(theta_q)*sin(x_q)
//   out0  = z1*z2*z3
//   out1  = z0*z1
//   out2  = z0*z1*z2
//   out3  = z0*z1*z2*z3
// Output layout: [NQ, B] float32.

#define SAMP_PER_THREAD 4

__global__ __launch_bounds__(256)
void quantum_layer_kernel(const float* __restrict__ x,
                          const float* __restrict__ w,
                          float* __restrict__ out,
                          int B) {
    __shared__ float sK[8];   // sK[0..3] = cos(theta_q), sK[4..7] = -cos(phi_q)*sin(theta_q)
    if (threadIdx.x < 4) {
        int q = threadIdx.x;
        float phi   = w[q * 3 + 0];
        float theta = w[q * 3 + 1];
        float st, ct;
        __sincosf(theta, &st, &ct);
        sK[q]     = ct;
        sK[q + 4] = -__cosf(phi) * st;
    }
    __syncthreads();

    const float kc0 = sK[0], kc1 = sK[1], kc2 = sK[2], kc3 = sK[3];
    const float ks0 = sK[4], ks1 = sK[5], ks2 = sK[6], ks3 = sK[7];

    int t = blockIdx.x * blockDim.x + threadIdx.x;
    int base = t * SAMP_PER_THREAD;          // first sample handled by this thread
    if (base >= B) return;

    float4 o0, o1, o2, o3;
    float* r0p = reinterpret_cast<float*>(&o0);
    float* r1p = reinterpret_cast<float*>(&o1);
    float* r2p = reinterpret_cast<float*>(&o2);
    float* r3p = reinterpret_cast<float*>(&o3);

    const float4* xv4 = reinterpret_cast<const float4*>(x);

#pragma unroll
    for (int j = 0; j < SAMP_PER_THREAD; ++j) {
        float4 xv = xv4[base + j];           // x0..x3 of sample base+j
        float s, c;
        __sincosf(xv.x, &s, &c); float z0 = fmaf(kc0, c, ks0 * s);
        __sincosf(xv.y, &s, &c); float z1 = fmaf(kc1, c, ks1 * s);
        __sincosf(xv.z, &s, &c); float z2 = fmaf(kc2, c, ks2 * s);
        __sincosf(xv.w, &s, &c); float z3 = fmaf(kc3, c, ks3 * s);

        float z12 = z1 * z2;
        r0p[j] = z12 * z3;      // z1 z2 z3
        float r1 = z0 * z1;
        r1p[j] = r1;            // z0 z1
        float r2 = r1 * z2;
        r2p[j] = r2;            // z0 z1 z2
        r3p[j] = r2 * z3;       // z0 z1 z2 z3
    }

    // out is [4, B]; each thread writes one float4 (4 consecutive samples) per row.
    reinterpret_cast<float4*>(out + 0 * (size_t)B)[t] = o0;
    reinterpret_cast<float4*>(out + 1 * (size_t)B)[t] = o1;
    reinterpret_cast<float4*>(out + 2 * (size_t)B)[t] = o2;
    reinterpret_cast<float4*>(out + 3 * (size_t)B)[t] = o3;
}

extern "C" void kernel_launch(void* const* d_in, const int* in_sizes, int n_in,
                              void* d_out, int out_size) {
    const float* x = (const float*)d_in[0];   // inputs  [B, 4] float32
    const float* w = (const float*)d_in[1];   // weights [1, 4, 3] float32
    float* out = (float*)d_out;               // [4, B] float32

    int B = in_sizes[0] / 4;                  // 1<<20
    int threads = 256;
    int total_threads = (B + SAMP_PER_THREAD - 1) / SAMP_PER_THREAD;
    int blocks = (total_threads + threads - 1) / threads;

    quantum_layer_kernel<<<blocks, threads>>>(x, w, out, B);
}

// round 2
// speedup vs baseline: 1.0504x; 1.0504x over previous
#include <cuda_runtime.h>

// QuantumLayer: 4-qubit circuit, closed-form.
//   z_q   = cos(theta_q)*cos(x_q) - cos(phi_q)*sin(theta_q)*sin(x_q)
//   out0  = z1*z2*z3
//   out1  = z0*z1
//   out2  = z0*z1*z2
//   out3  = z0*z1*z2*z3
// Output layout: [NQ, B] float32.
//
// Mapping (coalescing-first): each thread handles SAMP samples strided by
// blockDim within a block tile, so warp-level loads (float4 per sample) are
// lane-contiguous (16B stride -> 4 lines/LDG.128) and scalar stores per
// output row are lane-contiguous (4B stride -> 1 line/STG.32).

#define SAMP 4
#define TPB  256

__global__ __launch_bounds__(TPB)
void quantum_layer_kernel(const float* __restrict__ x,
                          const float* __restrict__ w,
                          float* __restrict__ out,
                          int B) {
    __shared__ float sK[8];   // [0..3] = cos(theta_q), [4..7] = -cos(phi_q)*sin(theta_q)
    if (threadIdx.x < 4) {
        int q = threadIdx.x;
        float phi   = w[q * 3 + 0];
        float theta = w[q * 3 + 1];
        float st, ct;
        __sincosf(theta, &st, &ct);
        sK[q]     = ct;
        sK[q + 4] = -__cosf(phi) * st;
    }
    __syncthreads();

    const float kc0 = sK[0], kc1 = sK[1], kc2 = sK[2], kc3 = sK[3];
    const float ks0 = sK[4], ks1 = sK[5], ks2 = sK[6], ks3 = sK[7];

    const float4* __restrict__ xv4 = reinterpret_cast<const float4*>(x);

    int tile = blockIdx.x * (TPB * SAMP);          // first sample of this block
    int i0   = tile + threadIdx.x;                 // this thread's first sample

    // Front-batch all loads (MLP=4, fully coalesced).
    float4 xv[SAMP];
#pragma unroll
    for (int j = 0; j < SAMP; ++j) {
        int i = i0 + j * TPB;
        if (i < B) xv[j] = xv4[i];
    }

    float r0[SAMP], r1[SAMP], r2[SAMP], r3[SAMP];
#pragma unroll
    for (int j = 0; j < SAMP; ++j) {
        float s, c;
        __sincosf(xv[j].x, &s, &c); float z0 = fmaf(kc0, c, ks0 * s);
        __sincosf(xv[j].y, &s, &c); float z1 = fmaf(kc1, c, ks1 * s);
        __sincosf(xv[j].z, &s, &c); float z2 = fmaf(kc2, c, ks2 * s);
        __sincosf(xv[j].w, &s, &c); float z3 = fmaf(kc3, c, ks3 * s);

        float z12 = z1 * z2;
        r0[j] = z12 * z3;            // z1 z2 z3
        float p01 = z0 * z1;
        r1[j] = p01;                 // z0 z1
        float p012 = p01 * z2;
        r2[j] = p012;                // z0 z1 z2
        r3[j] = p012 * z3;           // z0 z1 z2 z3
    }

    float* __restrict__ o0 = out;
    float* __restrict__ o1 = out + (size_t)B;
    float* __restrict__ o2 = out + 2 * (size_t)B;
    float* __restrict__ o3 = out + 3 * (size_t)B;

#pragma unroll
    for (int j = 0; j < SAMP; ++j) {
        int i = i0 + j * TPB;
        if (i < B) {
            o0[i] = r0[j];
            o1[i] = r1[j];
            o2[i] = r2[j];
            o3[i] = r3[j];
        }
    }
}

extern "C" void kernel_launch(void* const* d_in, const int* in_sizes, int n_in,
                              void* d_out, int out_size) {
    const float* x = (const float*)d_in[0];   // inputs  [B, 4] float32
    const float* w = (const float*)d_in[1];   // weights [1, 4, 3] float32
    float* out = (float*)d_out;               // [4, B] float32

    int B = in_sizes[0] / 4;                  // 1<<20
    int samplesPerBlock = TPB * SAMP;
    int blocks = (B + samplesPerBlock - 1) / samplesPerBlock;

    quantum_layer_kernel<<<blocks, TPB>>>(x, w, out, B);
}